// round 7
// baseline (speedup 1.0000x reference)
#include <cuda_runtime.h>

#define HH 384
#define WW 384
#define HO 382
#define WO 382
#define RPAD 5
#define TH 20    /* 8 + 2 + 2*RPAD */
#define TW 44    /* 32 + 2 + 2*RPAD */

typedef unsigned long long u64;

// Constant layout (floats):
// [0,540)    cwp[27][20]: conv weight pairs, cwp[jj*20+2p] = (w[2p][jj], w[2p+1][jj])
// [540,558)  conv-bias pairs at 540+2p
// [560,632)  dcn (c0,c1) pairs: (dcn_w[o][0][k], dcn_w[o][1][k]) at 560+k*8+2o (k-major, padded)
// [632,659)  dcn c2: dcn_w[o][2][k] at 632+k*3+o
// [660,663)  dcn bias
__constant__ __align__(16) float CW[672];
__device__ __align__(16) float d_scratch[672];

__device__ __forceinline__ u64 ffma2(u64 a, u64 b, u64 c){
    u64 d; asm("fma.rn.f32x2 %0,%1,%2,%3;" : "=l"(d) : "l"(a), "l"(b), "l"(c)); return d;
}
__device__ __forceinline__ u64 mul2(u64 a, u64 b){
    u64 d; asm("mul.rn.f32x2 %0,%1,%2;" : "=l"(d) : "l"(a), "l"(b)); return d;
}
__device__ __forceinline__ u64 add2(u64 a, u64 b){
    u64 d; asm("add.rn.f32x2 %0,%1,%2;" : "=l"(d) : "l"(a), "l"(b)); return d;
}
__device__ __forceinline__ u64 rep2(float x){
    u64 r; asm("mov.b64 %0,{%1,%1};" : "=l"(r) : "f"(x)); return r;
}
__device__ __forceinline__ u64 pack2(float a, float b){
    u64 r; asm("mov.b64 %0,{%1,%2};" : "=l"(r) : "f"(a), "f"(b)); return r;
}
__device__ __forceinline__ float2 unpack2(u64 v){
    float2 f; asm("mov.b64 {%0,%1},%2;" : "=f"(f.x), "=f"(f.y) : "l"(v)); return f;
}
__device__ __forceinline__ u64 ldc64(int foff){
    return *reinterpret_cast<const u64*>(&CW[foff]);
}
__device__ __forceinline__ ulonglong2 ldc128(int foff){
    return *reinterpret_cast<const ulonglong2*>(&CW[foff]);
}

__global__ void repack(const float* __restrict__ cw, const float* __restrict__ cb,
                       const float* __restrict__ dw, const float* __restrict__ db,
                       float* __restrict__ s)
{
    int t = threadIdx.x;
    if (t < 486) { int o = t / 27, jj = t % 27; s[jj * 20 + o] = cw[t]; }
    else if (t < 504) { s[540 + (t - 486)] = cb[t - 486]; }
    else if (t < 531) {
        int i = t - 504; int o = i / 9, k = i % 9;
        s[560 + k * 8 + 2 * o + 0] = dw[o * 27 + 0 + k];
        s[560 + k * 8 + 2 * o + 1] = dw[o * 27 + 9 + k];
        s[632 + k * 3 + o]         = dw[o * 27 + 18 + k];
    }
    else if (t < 534) { s[660 + (t - 531)] = db[t - 531]; }
    else if (t < 543) { int k = t - 534; s[560 + k * 8 + 6] = 0.f; s[560 + k * 8 + 7] = 0.f; }
}

// One bilinear sample -> packed (c0,c1) and scalar c2.
// INTERIOR: staged tile fully inside image => in-window implies in-image, no masks.
template<bool INTERIOR>
__device__ __forceinline__ void sample1(
    u64 off, float py0, float px0, int ybase, int xbase,
    const u64 (*tileP)[TW], const float (*tile2)[TW],
    const float* __restrict__ p0, const float* __restrict__ p1,
    const float* __restrict__ p2,
    u64& v01, float& v2)
{
    u64 pyx = add2(off, pack2(py0, px0));
    float2 q = unpack2(pyx);                       // (py, px)
    int y0 = __float2int_rd(q.x), x0 = __float2int_rd(q.y);
    float wy = q.x - (float)y0, wx = q.y - (float)x0;

    int ry = y0 - ybase, rx = x0 - xbase;
    bool inw = ((unsigned)ry < (unsigned)(TH - 1)) & ((unsigned)rx < (unsigned)(TW - 1));

    if (__builtin_expect(inw, 1)) {
        float a0, a1, b0, b1;
        if (INTERIOR) {
            a0 = 1.f - wy; a1 = wy; b0 = 1.f - wx; b1 = wx;
        } else {
            float vy0 = ((unsigned)y0       < (unsigned)HH) ? 1.f : 0.f;
            float vy1 = ((unsigned)(y0 + 1) < (unsigned)HH) ? 1.f : 0.f;
            float vx0 = ((unsigned)x0       < (unsigned)WW) ? 1.f : 0.f;
            float vx1 = ((unsigned)(x0 + 1) < (unsigned)WW) ? 1.f : 0.f;
            a0 = (1.f - wy) * vy0; a1 = wy * vy1;
            b0 = (1.f - wx) * vx0; b1 = wx * vx1;
        }
        float w00 = a0 * b0, w01 = a0 * b1, w10 = a1 * b0, w11 = a1 * b1;
        u64 t01 = mul2(tileP[ry][rx], rep2(w00));
        t01 = ffma2(tileP[ry][rx + 1],     rep2(w01), t01);
        t01 = ffma2(tileP[ry + 1][rx],     rep2(w10), t01);
        t01 = ffma2(tileP[ry + 1][rx + 1], rep2(w11), t01);
        v01 = t01;
        v2 = fmaf(tile2[ry + 1][rx + 1], w11,
             fmaf(tile2[ry + 1][rx],     w10,
             fmaf(tile2[ry][rx + 1],     w01, tile2[ry][rx] * w00)));
    } else {
        // Rare: outside staged window -> masked global path (any offsets).
        float vy0 = ((unsigned)y0       < (unsigned)HH) ? 1.f : 0.f;
        float vy1 = ((unsigned)(y0 + 1) < (unsigned)HH) ? 1.f : 0.f;
        float vx0 = ((unsigned)x0       < (unsigned)WW) ? 1.f : 0.f;
        float vx1 = ((unsigned)(x0 + 1) < (unsigned)WW) ? 1.f : 0.f;
        float a0 = (1.f - wy) * vy0, a1 = wy * vy1;
        float b0 = (1.f - wx) * vx0, b1 = wx * vx1;
        float w00 = a0 * b0, w01 = a0 * b1, w10 = a1 * b0, w11 = a1 * b1;
        int yc0 = min(max(y0, 0), HH - 1), yc1 = min(max(y0 + 1, 0), HH - 1);
        int xc0 = min(max(x0, 0), WW - 1), xc1 = min(max(x0 + 1, 0), WW - 1);
        int i00 = yc0 * WW + xc0, i01 = yc0 * WW + xc1;
        int i10 = yc1 * WW + xc0, i11 = yc1 * WW + xc1;
        u64 t01 = mul2(pack2(__ldg(p0 + i00), __ldg(p1 + i00)), rep2(w00));
        t01 = ffma2(pack2(__ldg(p0 + i01), __ldg(p1 + i01)), rep2(w01), t01);
        t01 = ffma2(pack2(__ldg(p0 + i10), __ldg(p1 + i10)), rep2(w10), t01);
        t01 = ffma2(pack2(__ldg(p0 + i11), __ldg(p1 + i11)), rep2(w11), t01);
        v01 = t01;
        v2 = fmaf(__ldg(p2 + i11), w11,
             fmaf(__ldg(p2 + i10), w10,
             fmaf(__ldg(p2 + i01), w01, __ldg(p2 + i00) * w00)));
    }
}

// Full deform + einsum for one pixel, fully unrolled (R4 schedule).
template<bool INTERIOR>
__device__ __forceinline__ void deform_body(
    const u64* __restrict__ off, float fi, float fj, int ybase, int xbase,
    const u64 (*tileP)[TW], const float (*tile2)[TW],
    const float* __restrict__ p0, const float* __restrict__ p1,
    const float* __restrict__ p2,
    float* __restrict__ res)
{
    u64 accP0 = 0, accP1 = 0, accP2 = 0;
    float a20 = CW[660], a21 = CW[661], a22 = CW[662];
    #pragma unroll
    for (int k = 0; k < 9; k++) {
        const int ky = k / 3, kx = k % 3;
        u64 v01; float v2;
        sample1<INTERIOR>(off[k], fi + (float)ky, fj + (float)kx,
                          ybase, xbase, tileP, tile2, p0, p1, p2, v01, v2);
        ulonglong2 wp01 = ldc128(560 + k * 8);   // (o=0 pair, o=1 pair)
        u64 wp2 = ldc64(560 + k * 8 + 4);        // o=2 pair
        accP0 = ffma2(v01, wp01.x, accP0);
        accP1 = ffma2(v01, wp01.y, accP1);
        accP2 = ffma2(v01, wp2,    accP2);
        a20 = fmaf(v2, CW[632 + k * 3 + 0], a20);
        a21 = fmaf(v2, CW[632 + k * 3 + 1], a21);
        a22 = fmaf(v2, CW[632 + k * 3 + 2], a22);
    }
    float2 r0 = unpack2(accP0), r1 = unpack2(accP1), r2 = unpack2(accP2);
    res[0] = r0.x + r0.y + a20;
    res[1] = r1.x + r1.y + a21;
    res[2] = r2.x + r2.y + a22;
}

// Cold path: one non-inlined copy shared by all border blocks (I$-safe).
__device__ __noinline__ void deform_border(
    const u64* __restrict__ off, float fi, float fj, int ybase, int xbase,
    const u64 (*tileP)[TW], const float (*tile2)[TW],
    const float* __restrict__ p0, const float* __restrict__ p1,
    const float* __restrict__ p2,
    float* __restrict__ res)
{
    deform_body<false>(off, fi, fj, ybase, xbase, tileP, tile2, p0, p1, p2, res);
}

__global__ __launch_bounds__(128, 6) void dcn_fused(
    const float* __restrict__ x, float* __restrict__ out)
{
    __shared__ u64   tileP[TH][TW];   // 7040 B
    __shared__ float tile2[TH][TW];   // 3520 B

    const int tx = threadIdx.x, ty = threadIdx.y;
    const int tid = ty * 32 + tx;
    const int i0 = blockIdx.y * 8, j0 = blockIdx.x * 32, b = blockIdx.z;
    const int ybase = i0 - RPAD, xbase = j0 - RPAD;

    const float* p0 = x + (size_t)b * 3 * HH * WW;
    const float* p1 = p0 + HH * WW;
    const float* p2 = p1 + HH * WW;

    // ---- Stage tile (border-clamped, x-coalesced) ----
    #pragma unroll
    for (int it = 0; it < 7; it++) {
        int idx = tid + it * 128;
        if (idx < TH * TW) {
            int r = idx / TW, q = idx % TW;
            int gy = min(max(ybase + r, 0), HH - 1);
            int gx = min(max(xbase + q, 0), WW - 1);
            int g = gy * WW + gx;
            tileP[r][q] = pack2(__ldg(p0 + g), __ldg(p1 + g));
            tile2[r][q] = __ldg(p2 + g);
        }
    }
    __syncthreads();

    const int j  = j0 + tx;
    const int iA = i0 + 2 * ty;
    if (j >= WO || iA >= HO) return;

    // ---- Offset conv for both pixels; each weight vector loaded ONCE ----
    u64 offA[9], offB[9];
    #pragma unroll
    for (int p = 0; p < 9; p++) { u64 bp = ldc64(540 + 2 * p); offA[p] = bp; offB[p] = bp; }

    const int lyA = 2 * ty + RPAD, lx = tx + RPAD;

    #pragma unroll
    for (int kx = 0; kx < 3; kx++) {
        u64 rp[4]; float r2[4];
        #pragma unroll
        for (int r = 0; r < 4; r++) { rp[r] = tileP[lyA + r][lx + kx]; r2[r] = tile2[lyA + r][lx + kx]; }
        #pragma unroll
        for (int ky = 0; ky < 3; ky++) {
            float2 fA = unpack2(rp[ky]);
            float2 fB = unpack2(rp[ky + 1]);
            #pragma unroll
            for (int c = 0; c < 3; c++) {
                const int jj = c * 9 + ky * 3 + kx;
                float xa = (c == 0) ? fA.x : (c == 1) ? fA.y : r2[ky];
                float xb = (c == 0) ? fB.x : (c == 1) ? fB.y : r2[ky + 1];
                u64 xa2 = rep2(xa), xb2 = rep2(xb);
                ulonglong2 v0 = ldc128(jj * 20 + 0);
                ulonglong2 v1 = ldc128(jj * 20 + 4);
                ulonglong2 v2 = ldc128(jj * 20 + 8);
                ulonglong2 v3 = ldc128(jj * 20 + 12);
                u64 p8 = ldc64(jj * 20 + 16);
                offA[0] = ffma2(xa2, v0.x, offA[0]); offB[0] = ffma2(xb2, v0.x, offB[0]);
                offA[1] = ffma2(xa2, v0.y, offA[1]); offB[1] = ffma2(xb2, v0.y, offB[1]);
                offA[2] = ffma2(xa2, v1.x, offA[2]); offB[2] = ffma2(xb2, v1.x, offB[2]);
                offA[3] = ffma2(xa2, v1.y, offA[3]); offB[3] = ffma2(xb2, v1.y, offB[3]);
                offA[4] = ffma2(xa2, v2.x, offA[4]); offB[4] = ffma2(xb2, v2.x, offB[4]);
                offA[5] = ffma2(xa2, v2.y, offA[5]); offB[5] = ffma2(xb2, v2.y, offB[5]);
                offA[6] = ffma2(xa2, v3.x, offA[6]); offB[6] = ffma2(xb2, v3.x, offB[6]);
                offA[7] = ffma2(xa2, v3.y, offA[7]); offB[7] = ffma2(xb2, v3.y, offB[7]);
                offA[8] = ffma2(xa2, p8,   offA[8]); offB[8] = ffma2(xb2, p8,   offB[8]);
            }
        }
    }

    // ---- Deform + einsum; interior blocks take the maskless inlined path ----
    const bool interior = (ybase >= 0) & (ybase + TH <= HH) & (xbase >= 0) & (xbase + TW <= WW);
    float rA[3], rB[3];
    const float fiA = (float)iA, fj = (float)j;
    if (__builtin_expect(interior, 1)) {
        deform_body<true>(offA, fiA,       fj, ybase, xbase, tileP, tile2, p0, p1, p2, rA);
        deform_body<true>(offB, fiA + 1.f, fj, ybase, xbase, tileP, tile2, p0, p1, p2, rB);
    } else {
        deform_border(offA, fiA,       fj, ybase, xbase, tileP, tile2, p0, p1, p2, rA);
        deform_border(offB, fiA + 1.f, fj, ybase, xbase, tileP, tile2, p0, p1, p2, rB);
    }

    const size_t plane = (size_t)HO * WO;
    size_t pa = (size_t)b * 3 * plane + (size_t)iA * WO + j;
    out[pa]             = rA[0];
    out[pa + plane]     = rA[1];
    out[pa + 2 * plane] = rA[2];
    pa += WO;
    out[pa]             = rB[0];
    out[pa + plane]     = rB[1];
    out[pa + 2 * plane] = rB[2];
}

extern "C" void kernel_launch(void* const* d_in, const int* in_sizes, int n_in,
                              void* d_out, int out_size)
{
    const float* x      = (const float*)d_in[0];
    const float* conv_w = (const float*)d_in[1];
    const float* conv_b = (const float*)d_in[2];
    const float* dcn_w  = (const float*)d_in[3];
    const float* dcn_b  = (const float*)d_in[4];
    float* out = (float*)d_out;

    float* sp = nullptr;  void* cp = nullptr;
    cudaGetSymbolAddress((void**)&sp, d_scratch);
    cudaGetSymbolAddress(&cp, CW);

    repack<<<1, 544>>>(conv_w, conv_b, dcn_w, dcn_b, sp);
    cudaMemcpyAsync(cp, sp, 672 * sizeof(float), cudaMemcpyDeviceToDevice);

    dim3 blk(32, 4);
    dim3 grd((WO + 31) / 32, (HO + 7) / 8, 16);
    dcn_fused<<<grd, blk>>>(x, out);
}

// round 8
// speedup vs baseline: 1.2478x; 1.2478x over previous
#include <cuda_runtime.h>

#define HH 384
#define WW 384
#define HO 382
#define WO 382
#define RPAD 5
#define TH 20    /* 8 + 2 + 2*RPAD */
#define TW 44    /* 32 + 2 + 2*RPAD */

typedef unsigned long long u64;

// Constant layout (floats):
// [0,540)    cwp[27][20]: conv weight pairs, cwp[jj*20+2p] = (w[2p][jj], w[2p+1][jj])
// [540,558)  conv-bias pairs at 540+2p
// [560,632)  dcn (c0,c1) pairs: (dcn_w[o][0][k], dcn_w[o][1][k]) at 560+k*8+2o (k-major, padded)
// [632,659)  dcn c2: dcn_w[o][2][k] at 632+k*3+o
// [660,663)  dcn bias
__constant__ __align__(16) float CW[672];
__device__ __align__(16) float d_scratch[672];

__device__ __forceinline__ u64 ffma2(u64 a, u64 b, u64 c){
    u64 d; asm("fma.rn.f32x2 %0,%1,%2,%3;" : "=l"(d) : "l"(a), "l"(b), "l"(c)); return d;
}
__device__ __forceinline__ u64 mul2(u64 a, u64 b){
    u64 d; asm("mul.rn.f32x2 %0,%1,%2;" : "=l"(d) : "l"(a), "l"(b)); return d;
}
__device__ __forceinline__ u64 add2(u64 a, u64 b){
    u64 d; asm("add.rn.f32x2 %0,%1,%2;" : "=l"(d) : "l"(a), "l"(b)); return d;
}
__device__ __forceinline__ u64 rep2(float x){
    u64 r; asm("mov.b64 %0,{%1,%1};" : "=l"(r) : "f"(x)); return r;
}
__device__ __forceinline__ u64 pack2(float a, float b){
    u64 r; asm("mov.b64 %0,{%1,%2};" : "=l"(r) : "f"(a), "f"(b)); return r;
}
__device__ __forceinline__ float2 unpack2(u64 v){
    float2 f; asm("mov.b64 {%0,%1},%2;" : "=f"(f.x), "=f"(f.y) : "l"(v)); return f;
}
__device__ __forceinline__ u64 ldc64(int foff){
    return *reinterpret_cast<const u64*>(&CW[foff]);
}
__device__ __forceinline__ ulonglong2 ldc128(int foff){
    return *reinterpret_cast<const ulonglong2*>(&CW[foff]);
}

__global__ void repack(const float* __restrict__ cw, const float* __restrict__ cb,
                       const float* __restrict__ dw, const float* __restrict__ db,
                       float* __restrict__ s)
{
    int t = threadIdx.x;
    if (t < 486) { int o = t / 27, jj = t % 27; s[jj * 20 + o] = cw[t]; }
    else if (t < 504) { s[540 + (t - 486)] = cb[t - 486]; }
    else if (t < 531) {
        int i = t - 504; int o = i / 9, k = i % 9;
        s[560 + k * 8 + 2 * o + 0] = dw[o * 27 + 0 + k];
        s[560 + k * 8 + 2 * o + 1] = dw[o * 27 + 9 + k];
        s[632 + k * 3 + o]         = dw[o * 27 + 18 + k];
    }
    else if (t < 534) { s[660 + (t - 531)] = db[t - 531]; }
    else if (t < 543) { int k = t - 534; s[560 + k * 8 + 6] = 0.f; s[560 + k * 8 + 7] = 0.f; }
}

// Offset conv for the 2-pixel pair (shared weight loads). R4 schedule.
__device__ __forceinline__ void conv_pair(
    const u64 (*tileP)[TW], const float (*tile2)[TW],
    int lyA, int lx, u64* offA, u64* offB)
{
    #pragma unroll
    for (int p = 0; p < 9; p++) { u64 bp = ldc64(540 + 2 * p); offA[p] = bp; offB[p] = bp; }
    #pragma unroll
    for (int kx = 0; kx < 3; kx++) {
        u64 rp[4]; float r2[4];
        #pragma unroll
        for (int r = 0; r < 4; r++) { rp[r] = tileP[lyA + r][lx + kx]; r2[r] = tile2[lyA + r][lx + kx]; }
        #pragma unroll
        for (int ky = 0; ky < 3; ky++) {
            float2 fA = unpack2(rp[ky]);
            float2 fB = unpack2(rp[ky + 1]);
            #pragma unroll
            for (int c = 0; c < 3; c++) {
                const int jj = c * 9 + ky * 3 + kx;
                float xa = (c == 0) ? fA.x : (c == 1) ? fA.y : r2[ky];
                float xb = (c == 0) ? fB.x : (c == 1) ? fB.y : r2[ky + 1];
                u64 xa2 = rep2(xa), xb2 = rep2(xb);
                ulonglong2 v0 = ldc128(jj * 20 + 0);
                ulonglong2 v1 = ldc128(jj * 20 + 4);
                ulonglong2 v2 = ldc128(jj * 20 + 8);
                ulonglong2 v3 = ldc128(jj * 20 + 12);
                u64 p8 = ldc64(jj * 20 + 16);
                offA[0] = ffma2(xa2, v0.x, offA[0]); offB[0] = ffma2(xb2, v0.x, offB[0]);
                offA[1] = ffma2(xa2, v0.y, offA[1]); offB[1] = ffma2(xb2, v0.y, offB[1]);
                offA[2] = ffma2(xa2, v1.x, offA[2]); offB[2] = ffma2(xb2, v1.x, offB[2]);
                offA[3] = ffma2(xa2, v1.y, offA[3]); offB[3] = ffma2(xb2, v1.y, offB[3]);
                offA[4] = ffma2(xa2, v2.x, offA[4]); offB[4] = ffma2(xb2, v2.x, offB[4]);
                offA[5] = ffma2(xa2, v2.y, offA[5]); offB[5] = ffma2(xb2, v2.y, offB[5]);
                offA[6] = ffma2(xa2, v3.x, offA[6]); offB[6] = ffma2(xb2, v3.x, offB[6]);
                offA[7] = ffma2(xa2, v3.y, offA[7]); offB[7] = ffma2(xb2, v3.y, offB[7]);
                offA[8] = ffma2(xa2, p8,   offA[8]); offB[8] = ffma2(xb2, p8,   offB[8]);
            }
        }
    }
}

// Deform + einsum for one pixel, fully unrolled, template-specialized on
// interiority. Single instantiation per kernel -> no I$ bloat, no ABI.
template<bool INTERIOR>
__device__ __forceinline__ void deform_one(
    const u64* off, float fi, float fj, int ybase, int xbase,
    const u64 (*tileP)[TW], const float (*tile2)[TW],
    const float* __restrict__ p0, const float* __restrict__ p1,
    const float* __restrict__ p2,
    float* res)
{
    u64 accP0 = 0, accP1 = 0, accP2 = 0;
    float a20 = CW[660], a21 = CW[661], a22 = CW[662];
    #pragma unroll
    for (int k = 0; k < 9; k++) {
        const int ky = k / 3, kx = k % 3;
        u64 pyx = add2(off[k], pack2(fi + (float)ky, fj + (float)kx));
        float2 q = unpack2(pyx);                   // (py, px)
        int y0 = __float2int_rd(q.x), x0 = __float2int_rd(q.y);
        float wy = q.x - (float)y0, wx = q.y - (float)x0;
        int ry = y0 - ybase, rx = x0 - xbase;
        bool inw = ((unsigned)ry < (unsigned)(TH - 1)) & ((unsigned)rx < (unsigned)(TW - 1));

        u64 v01; float v2;
        if (__builtin_expect(inw, 1)) {
            float a0, a1, b0, b1;
            if (INTERIOR) {                        // tile inside image: no masks
                a0 = 1.f - wy; a1 = wy; b0 = 1.f - wx; b1 = wx;
            } else {
                float vy0 = ((unsigned)y0       < (unsigned)HH) ? 1.f : 0.f;
                float vy1 = ((unsigned)(y0 + 1) < (unsigned)HH) ? 1.f : 0.f;
                float vx0 = ((unsigned)x0       < (unsigned)WW) ? 1.f : 0.f;
                float vx1 = ((unsigned)(x0 + 1) < (unsigned)WW) ? 1.f : 0.f;
                a0 = (1.f - wy) * vy0; a1 = wy * vy1;
                b0 = (1.f - wx) * vx0; b1 = wx * vx1;
            }
            float w00 = a0 * b0, w01 = a0 * b1, w10 = a1 * b0, w11 = a1 * b1;
            u64 t01 = mul2(tileP[ry][rx], rep2(w00));
            t01 = ffma2(tileP[ry][rx + 1],     rep2(w01), t01);
            t01 = ffma2(tileP[ry + 1][rx],     rep2(w10), t01);
            t01 = ffma2(tileP[ry + 1][rx + 1], rep2(w11), t01);
            v01 = t01;
            v2 = fmaf(tile2[ry + 1][rx + 1], w11,
                 fmaf(tile2[ry + 1][rx],     w10,
                 fmaf(tile2[ry][rx + 1],     w01, tile2[ry][rx] * w00)));
        } else {
            // Rare: out of staged window -> masked global path (any offsets).
            float vy0 = ((unsigned)y0       < (unsigned)HH) ? 1.f : 0.f;
            float vy1 = ((unsigned)(y0 + 1) < (unsigned)HH) ? 1.f : 0.f;
            float vx0 = ((unsigned)x0       < (unsigned)WW) ? 1.f : 0.f;
            float vx1 = ((unsigned)(x0 + 1) < (unsigned)WW) ? 1.f : 0.f;
            float a0 = (1.f - wy) * vy0, a1 = wy * vy1;
            float b0 = (1.f - wx) * vx0, b1 = wx * vx1;
            float w00 = a0 * b0, w01 = a0 * b1, w10 = a1 * b0, w11 = a1 * b1;
            int yc0 = min(max(y0, 0), HH - 1), yc1 = min(max(y0 + 1, 0), HH - 1);
            int xc0 = min(max(x0, 0), WW - 1), xc1 = min(max(x0 + 1, 0), WW - 1);
            int i00 = yc0 * WW + xc0, i01 = yc0 * WW + xc1;
            int i10 = yc1 * WW + xc0, i11 = yc1 * WW + xc1;
            u64 t01 = mul2(pack2(__ldg(p0 + i00), __ldg(p1 + i00)), rep2(w00));
            t01 = ffma2(pack2(__ldg(p0 + i01), __ldg(p1 + i01)), rep2(w01), t01);
            t01 = ffma2(pack2(__ldg(p0 + i10), __ldg(p1 + i10)), rep2(w10), t01);
            t01 = ffma2(pack2(__ldg(p0 + i11), __ldg(p1 + i11)), rep2(w11), t01);
            v01 = t01;
            v2 = fmaf(__ldg(p2 + i11), w11,
                 fmaf(__ldg(p2 + i10), w10,
                 fmaf(__ldg(p2 + i01), w01, __ldg(p2 + i00) * w00)));
        }

        ulonglong2 wp01 = ldc128(560 + k * 8);
        u64 wp2 = ldc64(560 + k * 8 + 4);
        accP0 = ffma2(v01, wp01.x, accP0);
        accP1 = ffma2(v01, wp01.y, accP1);
        accP2 = ffma2(v01, wp2,    accP2);
        a20 = fmaf(v2, CW[632 + k * 3 + 0], a20);
        a21 = fmaf(v2, CW[632 + k * 3 + 1], a21);
        a22 = fmaf(v2, CW[632 + k * 3 + 2], a22);
    }
    float2 r0 = unpack2(accP0), r1 = unpack2(accP1), r2 = unpack2(accP2);
    res[0] = r0.x + r0.y + a20;
    res[1] = r1.x + r1.y + a21;
    res[2] = r2.x + r2.y + a22;
}

// ---- Interior kernel: tile provably inside image. No clamps, no masks,
// no output bounds checks. Grid (10,45,16), block indices offset by (1,1). ----
__global__ __launch_bounds__(128, 6) void dcn_interior(
    const float* __restrict__ x, float* __restrict__ out)
{
    __shared__ u64   tileP[TH][TW];
    __shared__ float tile2[TH][TW];

    const int tx = threadIdx.x, ty = threadIdx.y;
    const int tid = ty * 32 + tx;
    const int i0 = (blockIdx.y + 1) * 8, j0 = (blockIdx.x + 1) * 32, b = blockIdx.z;
    const int ybase = i0 - RPAD, xbase = j0 - RPAD;

    const float* p0 = x + (size_t)b * 3 * HH * WW;
    const float* p1 = p0 + HH * WW;
    const float* p2 = p1 + HH * WW;

    #pragma unroll
    for (int it = 0; it < 7; it++) {
        int idx = tid + it * 128;
        if (idx < TH * TW) {
            int r = idx / TW, q = idx % TW;
            int g = (ybase + r) * WW + (xbase + q);   // always in-image
            tileP[r][q] = pack2(__ldg(p0 + g), __ldg(p1 + g));
            tile2[r][q] = __ldg(p2 + g);
        }
    }
    __syncthreads();

    const int j  = j0 + tx;
    const int iA = i0 + 2 * ty;

    u64 offA[9], offB[9];
    conv_pair(tileP, tile2, 2 * ty + RPAD, tx + RPAD, offA, offB);

    float rA[3], rB[3];
    const float fiA = (float)iA, fj = (float)j;
    deform_one<true>(offA, fiA,       fj, ybase, xbase, tileP, tile2, p0, p1, p2, rA);
    deform_one<true>(offB, fiA + 1.f, fj, ybase, xbase, tileP, tile2, p0, p1, p2, rB);

    const size_t plane = (size_t)HO * WO;
    size_t pa = (size_t)b * 3 * plane + (size_t)iA * WO + j;
    out[pa]             = rA[0];
    out[pa + plane]     = rA[1];
    out[pa + 2 * plane] = rA[2];
    pa += WO;
    out[pa]             = rB[0];
    out[pa + plane]     = rB[1];
    out[pa + 2 * plane] = rB[2];
}

// ---- Border kernel: full grid; interior blocks exit immediately. ----
__global__ __launch_bounds__(128, 6) void dcn_border(
    const float* __restrict__ x, float* __restrict__ out)
{
    const int bx = blockIdx.x, by = blockIdx.y;
    if ((bx >= 1) & (bx <= 10) & (by >= 1) & (by <= 45)) return;  // interior: handled elsewhere

    __shared__ u64   tileP[TH][TW];
    __shared__ float tile2[TH][TW];

    const int tx = threadIdx.x, ty = threadIdx.y;
    const int tid = ty * 32 + tx;
    const int i0 = by * 8, j0 = bx * 32, b = blockIdx.z;
    const int ybase = i0 - RPAD, xbase = j0 - RPAD;

    const float* p0 = x + (size_t)b * 3 * HH * WW;
    const float* p1 = p0 + HH * WW;
    const float* p2 = p1 + HH * WW;

    #pragma unroll
    for (int it = 0; it < 7; it++) {
        int idx = tid + it * 128;
        if (idx < TH * TW) {
            int r = idx / TW, q = idx % TW;
            int gy = min(max(ybase + r, 0), HH - 1);
            int gx = min(max(xbase + q, 0), WW - 1);
            int g = gy * WW + gx;
            tileP[r][q] = pack2(__ldg(p0 + g), __ldg(p1 + g));
            tile2[r][q] = __ldg(p2 + g);
        }
    }
    __syncthreads();

    const int j  = j0 + tx;
    const int iA = i0 + 2 * ty;
    if (j >= WO || iA >= HO) return;

    u64 offA[9], offB[9];
    conv_pair(tileP, tile2, 2 * ty + RPAD, tx + RPAD, offA, offB);

    float rA[3], rB[3];
    const float fiA = (float)iA, fj = (float)j;
    deform_one<false>(offA, fiA,       fj, ybase, xbase, tileP, tile2, p0, p1, p2, rA);
    deform_one<false>(offB, fiA + 1.f, fj, ybase, xbase, tileP, tile2, p0, p1, p2, rB);

    const size_t plane = (size_t)HO * WO;
    size_t pa = (size_t)b * 3 * plane + (size_t)iA * WO + j;
    out[pa]             = rA[0];
    out[pa + plane]     = rA[1];
    out[pa + 2 * plane] = rA[2];
    pa += WO;
    out[pa]             = rB[0];
    out[pa + plane]     = rB[1];
    out[pa + 2 * plane] = rB[2];
}

extern "C" void kernel_launch(void* const* d_in, const int* in_sizes, int n_in,
                              void* d_out, int out_size)
{
    const float* x      = (const float*)d_in[0];
    const float* conv_w = (const float*)d_in[1];
    const float* conv_b = (const float*)d_in[2];
    const float* dcn_w  = (const float*)d_in[3];
    const float* dcn_b  = (const float*)d_in[4];
    float* out = (float*)d_out;

    float* sp = nullptr;  void* cp = nullptr;
    cudaGetSymbolAddress((void**)&sp, d_scratch);
    cudaGetSymbolAddress(&cp, CW);

    repack<<<1, 544>>>(conv_w, conv_b, dcn_w, dcn_b, sp);
    cudaMemcpyAsync(cp, sp, 672 * sizeof(float), cudaMemcpyDeviceToDevice);

    dim3 blk(32, 4);
    dcn_interior<<<dim3(10, 45, 16), blk>>>(x, out);
    dcn_border  <<<dim3(12, 48, 16), blk>>>(x, out);
}

// round 9
// speedup vs baseline: 1.3482x; 1.0804x over previous
#include <cuda_runtime.h>

#define HH 384
#define WW 384
#define HO 382
#define WO 382
#define RPAD 5
#define TH 20    /* 8 + 2 + 2*RPAD */
#define TW 44    /* 32 + 2 + 2*RPAD */

typedef unsigned long long u64;

// Constant layout (floats):
// [0,540)    cwp[27][20]: conv weight pairs, cwp[jj*20+2p] = (w[2p][jj], w[2p+1][jj])
// [540,558)  conv-bias pairs at 540+2p
// [560,632)  dcn (c0,c1) pairs: (dcn_w[o][0][k], dcn_w[o][1][k]) at 560+k*8+2o (k-major, padded)
// [632,659)  dcn c2: dcn_w[o][2][k] at 632+k*3+o
// [660,663)  dcn bias
__constant__ __align__(16) float CW[672];
__device__ __align__(16) float d_scratch[672];

__device__ __forceinline__ u64 ffma2(u64 a, u64 b, u64 c){
    u64 d; asm("fma.rn.f32x2 %0,%1,%2,%3;" : "=l"(d) : "l"(a), "l"(b), "l"(c)); return d;
}
__device__ __forceinline__ u64 mul2(u64 a, u64 b){
    u64 d; asm("mul.rn.f32x2 %0,%1,%2;" : "=l"(d) : "l"(a), "l"(b)); return d;
}
__device__ __forceinline__ u64 add2(u64 a, u64 b){
    u64 d; asm("add.rn.f32x2 %0,%1,%2;" : "=l"(d) : "l"(a), "l"(b)); return d;
}
__device__ __forceinline__ u64 rep2(float x){
    u64 r; asm("mov.b64 %0,{%1,%1};" : "=l"(r) : "f"(x)); return r;
}
__device__ __forceinline__ u64 pack2(float a, float b){
    u64 r; asm("mov.b64 %0,{%1,%2};" : "=l"(r) : "f"(a), "f"(b)); return r;
}
__device__ __forceinline__ float2 unpack2(u64 v){
    float2 f; asm("mov.b64 {%0,%1},%2;" : "=f"(f.x), "=f"(f.y) : "l"(v)); return f;
}
__device__ __forceinline__ u64 ldc64(int foff){
    return *reinterpret_cast<const u64*>(&CW[foff]);
}
__device__ __forceinline__ ulonglong2 ldc128(int foff){
    return *reinterpret_cast<const ulonglong2*>(&CW[foff]);
}

__global__ void repack(const float* __restrict__ cw, const float* __restrict__ cb,
                       const float* __restrict__ dw, const float* __restrict__ db,
                       float* __restrict__ s)
{
    int t = threadIdx.x;
    if (t < 486) { int o = t / 27, jj = t % 27; s[jj * 20 + o] = cw[t]; }
    else if (t < 504) { s[540 + (t - 486)] = cb[t - 486]; }
    else if (t < 531) {
        int i = t - 504; int o = i / 9, k = i % 9;
        s[560 + k * 8 + 2 * o + 0] = dw[o * 27 + 0 + k];
        s[560 + k * 8 + 2 * o + 1] = dw[o * 27 + 9 + k];
        s[632 + k * 3 + o]         = dw[o * 27 + 18 + k];
    }
    else if (t < 534) { s[660 + (t - 531)] = db[t - 531]; }
    else if (t < 543) { int k = t - 534; s[560 + k * 8 + 6] = 0.f; s[560 + k * 8 + 7] = 0.f; }
}

// Fused offset-conv + deformable conv. Block = 32x4 threads, each thread does
// 2 vertically adjacent pixels -> 32x8 output tile. Split smem tile:
// (c0,c1) as u64 + c2 scalar. Weights in __constant__, loaded once per thread.
// R4 schedule, occupancy raised 4 -> 6 blocks/SM (84 regs fits the 85 cap).
__global__ __launch_bounds__(128, 6) void dcn_fused(
    const float* __restrict__ x, float* __restrict__ out)
{
    __shared__ u64   tileP[TH][TW];   // 7040 B
    __shared__ float tile2[TH][TW];   // 3520 B

    const int tx = threadIdx.x, ty = threadIdx.y;
    const int tid = ty * 32 + tx;
    const int i0 = blockIdx.y * 8, j0 = blockIdx.x * 32, b = blockIdx.z;
    const int ybase = i0 - RPAD, xbase = j0 - RPAD;

    const float* p0 = x + (size_t)b * 3 * HH * WW;
    const float* p1 = p0 + HH * WW;
    const float* p2 = p1 + HH * WW;

    // ---- Stage tile (border-clamped; clamp doubles as border handling later) ----
    #pragma unroll
    for (int it = 0; it < 7; it++) {
        int idx = tid + it * 128;
        if (idx < TH * TW) {
            int r = idx / TW, q = idx % TW;
            int gy = min(max(ybase + r, 0), HH - 1);
            int gx = min(max(xbase + q, 0), WW - 1);
            int g = gy * WW + gx;
            tileP[r][q] = pack2(__ldg(p0 + g), __ldg(p1 + g));
            tile2[r][q] = __ldg(p2 + g);
        }
    }
    __syncthreads();

    const int j  = j0 + tx;
    const int iA = i0 + 2 * ty;            // even; iB = iA+1. Both valid or both not.
    if (j >= WO || iA >= HO) return;

    // ---- Offset conv for both pixels; each weight vector loaded ONCE ----
    u64 offA[9], offB[9];
    #pragma unroll
    for (int p = 0; p < 9; p++) { u64 bp = ldc64(540 + 2 * p); offA[p] = bp; offB[p] = bp; }

    const int lyA = 2 * ty + RPAD, lx = tx + RPAD;

    #pragma unroll
    for (int kx = 0; kx < 3; kx++) {
        u64 rp[4]; float r2[4];
        #pragma unroll
        for (int r = 0; r < 4; r++) { rp[r] = tileP[lyA + r][lx + kx]; r2[r] = tile2[lyA + r][lx + kx]; }
        #pragma unroll
        for (int ky = 0; ky < 3; ky++) {
            float2 fA = unpack2(rp[ky]);
            float2 fB = unpack2(rp[ky + 1]);
            #pragma unroll
            for (int c = 0; c < 3; c++) {
                const int jj = c * 9 + ky * 3 + kx;
                float xa = (c == 0) ? fA.x : (c == 1) ? fA.y : r2[ky];
                float xb = (c == 0) ? fB.x : (c == 1) ? fB.y : r2[ky + 1];
                u64 xa2 = rep2(xa), xb2 = rep2(xb);
                ulonglong2 v0 = ldc128(jj * 20 + 0);
                ulonglong2 v1 = ldc128(jj * 20 + 4);
                ulonglong2 v2 = ldc128(jj * 20 + 8);
                ulonglong2 v3 = ldc128(jj * 20 + 12);
                u64 p8 = ldc64(jj * 20 + 16);
                offA[0] = ffma2(xa2, v0.x, offA[0]); offB[0] = ffma2(xb2, v0.x, offB[0]);
                offA[1] = ffma2(xa2, v0.y, offA[1]); offB[1] = ffma2(xb2, v0.y, offB[1]);
                offA[2] = ffma2(xa2, v1.x, offA[2]); offB[2] = ffma2(xb2, v1.x, offB[2]);
                offA[3] = ffma2(xa2, v1.y, offA[3]); offB[3] = ffma2(xb2, v1.y, offB[3]);
                offA[4] = ffma2(xa2, v2.x, offA[4]); offB[4] = ffma2(xb2, v2.x, offB[4]);
                offA[5] = ffma2(xa2, v2.y, offA[5]); offB[5] = ffma2(xb2, v2.y, offB[5]);
                offA[6] = ffma2(xa2, v3.x, offA[6]); offB[6] = ffma2(xb2, v3.x, offB[6]);
                offA[7] = ffma2(xa2, v3.y, offA[7]); offB[7] = ffma2(xb2, v3.y, offB[7]);
                offA[8] = ffma2(xa2, p8,   offA[8]); offB[8] = ffma2(xb2, p8,   offB[8]);
            }
        }
    }

    // ---- Deformable sampling + einsum for one pixel ----
    const float fj = (float)j;
    auto deform = [&](const u64* off, float fi, float* res) {
        u64 accP0 = 0ULL, accP1 = 0ULL, accP2 = 0ULL;
        float a20 = CW[660], a21 = CW[661], a22 = CW[662];
        #pragma unroll
        for (int k = 0; k < 9; k++) {
            const int ky = k / 3, kx = k % 3;
            u64 pyx = add2(off[k], pack2(fi + (float)ky, fj + (float)kx));
            float2 q = unpack2(pyx);                      // (py, px)
            int y0 = __float2int_rd(q.x), x0 = __float2int_rd(q.y);
            float wy = q.x - (float)y0, wx = q.y - (float)x0;
            float vy0 = ((unsigned)y0       < (unsigned)HH) ? 1.f : 0.f;
            float vy1 = ((unsigned)(y0 + 1) < (unsigned)HH) ? 1.f : 0.f;
            float vx0 = ((unsigned)x0       < (unsigned)WW) ? 1.f : 0.f;
            float vx1 = ((unsigned)(x0 + 1) < (unsigned)WW) ? 1.f : 0.f;
            float a0 = (1.f - wy) * vy0, a1 = wy * vy1;
            float b0 = (1.f - wx) * vx0, b1 = wx * vx1;
            float w00 = a0 * b0, w01 = a0 * b1, w10 = a1 * b0, w11 = a1 * b1;

            int ry = y0 - ybase, rx = x0 - xbase;         // tile-local; staging clamp
            u64 gP00, gP01, gP10, gP11;                   // already border-clamps values
            float gs00, gs01, gs10, gs11;
            if (__builtin_expect(((unsigned)ry < (unsigned)(TH - 1)) &
                                 ((unsigned)rx < (unsigned)(TW - 1)), 1)) {
                gP00 = tileP[ry][rx];     gP01 = tileP[ry][rx + 1];
                gP10 = tileP[ry + 1][rx]; gP11 = tileP[ry + 1][rx + 1];
                gs00 = tile2[ry][rx];     gs01 = tile2[ry][rx + 1];
                gs10 = tile2[ry + 1][rx]; gs11 = tile2[ry + 1][rx + 1];
            } else {
                int yc0 = min(max(y0, 0), HH - 1), yc1 = min(max(y0 + 1, 0), HH - 1);
                int xc0 = min(max(x0, 0), WW - 1), xc1 = min(max(x0 + 1, 0), WW - 1);
                int i00 = yc0 * WW + xc0, i01 = yc0 * WW + xc1;
                int i10 = yc1 * WW + xc0, i11 = yc1 * WW + xc1;
                gP00 = pack2(__ldg(p0 + i00), __ldg(p1 + i00)); gs00 = __ldg(p2 + i00);
                gP01 = pack2(__ldg(p0 + i01), __ldg(p1 + i01)); gs01 = __ldg(p2 + i01);
                gP10 = pack2(__ldg(p0 + i10), __ldg(p1 + i10)); gs10 = __ldg(p2 + i10);
                gP11 = pack2(__ldg(p0 + i11), __ldg(p1 + i11)); gs11 = __ldg(p2 + i11);
            }

            u64 v01 = mul2(gP00, rep2(w00));
            v01 = ffma2(gP01, rep2(w01), v01);
            v01 = ffma2(gP10, rep2(w10), v01);
            v01 = ffma2(gP11, rep2(w11), v01);
            float v2 = fmaf(gs11, w11, fmaf(gs10, w10, fmaf(gs01, w01, gs00 * w00)));

            ulonglong2 wp01 = ldc128(560 + k * 8);        // (o=0 pair, o=1 pair)
            u64 wp2 = ldc64(560 + k * 8 + 4);             // o=2 pair
            accP0 = ffma2(v01, wp01.x, accP0);
            accP1 = ffma2(v01, wp01.y, accP1);
            accP2 = ffma2(v01, wp2,   accP2);
            a20 = fmaf(v2, CW[632 + k * 3 + 0], a20);
            a21 = fmaf(v2, CW[632 + k * 3 + 1], a21);
            a22 = fmaf(v2, CW[632 + k * 3 + 2], a22);
        }
        float2 r0 = unpack2(accP0), r1 = unpack2(accP1), r2 = unpack2(accP2);
        res[0] = r0.x + r0.y + a20;
        res[1] = r1.x + r1.y + a21;
        res[2] = r2.x + r2.y + a22;
    };

    float rA[3], rB[3];
    deform(offA, (float)iA,        rA);
    deform(offB, (float)iA + 1.f,  rB);

    const size_t plane = (size_t)HO * WO;
    size_t pa = (size_t)b * 3 * plane + (size_t)iA * WO + j;
    out[pa]             = rA[0];
    out[pa + plane]     = rA[1];
    out[pa + 2 * plane] = rA[2];
    pa += WO;
    out[pa]             = rB[0];
    out[pa + plane]     = rB[1];
    out[pa + 2 * plane] = rB[2];
}

extern "C" void kernel_launch(void* const* d_in, const int* in_sizes, int n_in,
                              void* d_out, int out_size)
{
    const float* x      = (const float*)d_in[0];
    const float* conv_w = (const float*)d_in[1];
    const float* conv_b = (const float*)d_in[2];
    const float* dcn_w  = (const float*)d_in[3];
    const float* dcn_b  = (const float*)d_in[4];
    float* out = (float*)d_out;

    float* sp = nullptr;  void* cp = nullptr;
    cudaGetSymbolAddress((void**)&sp, d_scratch);
    cudaGetSymbolAddress(&cp, CW);

    repack<<<1, 544>>>(conv_w, conv_b, dcn_w, dcn_b, sp);
    cudaMemcpyAsync(cp, sp, 672 * sizeof(float), cudaMemcpyDeviceToDevice);

    dim3 blk(32, 4);
    dim3 grd((WO + 31) / 32, (HO + 7) / 8, 16);
    dcn_fused<<<grd, blk>>>(x, out);
}

// round 10
// speedup vs baseline: 1.3959x; 1.0354x over previous
#include <cuda_runtime.h>

#define HH 384
#define WW 384
#define HO 382
#define WO 382
#define RPAD 5
#define TH 20    /* 8 + 2 + 2*RPAD */
#define TW 44    /* 32 + 2 + 2*RPAD */

typedef unsigned long long u64;

// Constant layout (floats):
// [0,540)    cwp[27][20]: conv weight pairs, cwp[jj*20+2p] = (w[2p][jj], w[2p+1][jj])
// [540,558)  conv-bias pairs at 540+2p
// [560,632)  dcn (c0,c1) pairs: (dcn_w[o][0][k], dcn_w[o][1][k]) at 560+k*8+2o (k-major, padded)
// [632,659)  dcn c2: dcn_w[o][2][k] at 632+k*3+o
// [660,663)  dcn bias
__constant__ __align__(16) float CW[672];
__device__ __align__(16) float d_scratch[672];

__device__ __forceinline__ u64 ffma2(u64 a, u64 b, u64 c){
    u64 d; asm("fma.rn.f32x2 %0,%1,%2,%3;" : "=l"(d) : "l"(a), "l"(b), "l"(c)); return d;
}
__device__ __forceinline__ u64 mul2(u64 a, u64 b){
    u64 d; asm("mul.rn.f32x2 %0,%1,%2;" : "=l"(d) : "l"(a), "l"(b)); return d;
}
__device__ __forceinline__ u64 add2(u64 a, u64 b){
    u64 d; asm("add.rn.f32x2 %0,%1,%2;" : "=l"(d) : "l"(a), "l"(b)); return d;
}
__device__ __forceinline__ u64 rep2(float x){
    u64 r; asm("mov.b64 %0,{%1,%1};" : "=l"(r) : "f"(x)); return r;
}
__device__ __forceinline__ u64 pack2(float a, float b){
    u64 r; asm("mov.b64 %0,{%1,%2};" : "=l"(r) : "f"(a), "f"(b)); return r;
}
__device__ __forceinline__ float2 unpack2(u64 v){
    float2 f; asm("mov.b64 {%0,%1},%2;" : "=f"(f.x), "=f"(f.y) : "l"(v)); return f;
}
__device__ __forceinline__ u64 ldc64(int foff){
    return *reinterpret_cast<const u64*>(&CW[foff]);
}
__device__ __forceinline__ ulonglong2 ldc128(int foff){
    return *reinterpret_cast<const ulonglong2*>(&CW[foff]);
}

__global__ void repack(const float* __restrict__ cw, const float* __restrict__ cb,
                       const float* __restrict__ dw, const float* __restrict__ db,
                       float* __restrict__ s)
{
    int t = threadIdx.x;
    if (t < 486) { int o = t / 27, jj = t % 27; s[jj * 20 + o] = cw[t]; }
    else if (t < 504) { s[540 + (t - 486)] = cb[t - 486]; }
    else if (t < 531) {
        int i = t - 504; int o = i / 9, k = i % 9;
        s[560 + k * 8 + 2 * o + 0] = dw[o * 27 + 0 + k];
        s[560 + k * 8 + 2 * o + 1] = dw[o * 27 + 9 + k];
        s[632 + k * 3 + o]         = dw[o * 27 + 18 + k];
    }
    else if (t < 534) { s[660 + (t - 531)] = db[t - 531]; }
    else if (t < 543) { int k = t - 534; s[560 + k * 8 + 6] = 0.f; s[560 + k * 8 + 7] = 0.f; }
}

// Fused offset-conv + deformable conv. Block = 32x4 threads, 2 vertically
// adjacent pixels per thread -> 32x8 output tile.
// KEY: tile is staged ZERO-PADDED (0 outside the image). The reference's
// bilinear masks value*valid == bilinear over a zero-extended image, so the
// in-window sampling path needs NO validity masks at all (12 instr/tap saved).
// Offset-conv taps are always in-image (VALID conv), so they still read real
// values. Out-of-window samples fall back to the masked global path (rare).
__global__ __launch_bounds__(128, 6) void dcn_fused(
    const float* __restrict__ x, float* __restrict__ out)
{
    __shared__ u64   tileP[TH][TW];   // 7040 B  (c0,c1) pairs
    __shared__ float tile2[TH][TW];   // 3520 B  c2

    const int tx = threadIdx.x, ty = threadIdx.y;
    const int tid = ty * 32 + tx;
    const int i0 = blockIdx.y * 8, j0 = blockIdx.x * 32, b = blockIdx.z;
    const int ybase = i0 - RPAD, xbase = j0 - RPAD;

    const float* p0 = x + (size_t)b * 3 * HH * WW;
    const float* p1 = p0 + HH * WW;
    const float* p2 = p1 + HH * WW;

    // ---- Stage tile, ZERO outside the image (zero-extension semantics) ----
    #pragma unroll
    for (int it = 0; it < 7; it++) {
        int idx = tid + it * 128;
        if (idx < TH * TW) {
            int r = idx / TW, q = idx % TW;
            int gy = ybase + r, gx = xbase + q;
            bool vin = ((unsigned)gy < (unsigned)HH) & ((unsigned)gx < (unsigned)WW);
            int g = min(max(gy, 0), HH - 1) * WW + min(max(gx, 0), WW - 1);
            float m = vin ? 1.f : 0.f;
            tileP[r][q] = pack2(__ldg(p0 + g) * m, __ldg(p1 + g) * m);
            tile2[r][q] = __ldg(p2 + g) * m;
        }
    }
    __syncthreads();

    const int j  = j0 + tx;
    const int iA = i0 + 2 * ty;            // even; iB = iA+1. Both valid or both not.
    if (j >= WO || iA >= HO) return;

    // ---- Offset conv for both pixels; each weight vector loaded ONCE ----
    u64 offA[9], offB[9];
    #pragma unroll
    for (int p = 0; p < 9; p++) { u64 bp = ldc64(540 + 2 * p); offA[p] = bp; offB[p] = bp; }

    const int lyA = 2 * ty + RPAD, lx = tx + RPAD;

    #pragma unroll
    for (int kx = 0; kx < 3; kx++) {
        u64 rp[4]; float r2[4];
        #pragma unroll
        for (int r = 0; r < 4; r++) { rp[r] = tileP[lyA + r][lx + kx]; r2[r] = tile2[lyA + r][lx + kx]; }
        #pragma unroll
        for (int ky = 0; ky < 3; ky++) {
            float2 fA = unpack2(rp[ky]);
            float2 fB = unpack2(rp[ky + 1]);
            #pragma unroll
            for (int c = 0; c < 3; c++) {
                const int jj = c * 9 + ky * 3 + kx;
                float xa = (c == 0) ? fA.x : (c == 1) ? fA.y : r2[ky];
                float xb = (c == 0) ? fB.x : (c == 1) ? fB.y : r2[ky + 1];
                u64 xa2 = rep2(xa), xb2 = rep2(xb);
                ulonglong2 v0 = ldc128(jj * 20 + 0);
                ulonglong2 v1 = ldc128(jj * 20 + 4);
                ulonglong2 v2 = ldc128(jj * 20 + 8);
                ulonglong2 v3 = ldc128(jj * 20 + 12);
                u64 p8 = ldc64(jj * 20 + 16);
                offA[0] = ffma2(xa2, v0.x, offA[0]); offB[0] = ffma2(xb2, v0.x, offB[0]);
                offA[1] = ffma2(xa2, v0.y, offA[1]); offB[1] = ffma2(xb2, v0.y, offB[1]);
                offA[2] = ffma2(xa2, v1.x, offA[2]); offB[2] = ffma2(xb2, v1.x, offB[2]);
                offA[3] = ffma2(xa2, v1.y, offA[3]); offB[3] = ffma2(xb2, v1.y, offB[3]);
                offA[4] = ffma2(xa2, v2.x, offA[4]); offB[4] = ffma2(xb2, v2.x, offB[4]);
                offA[5] = ffma2(xa2, v2.y, offA[5]); offB[5] = ffma2(xb2, v2.y, offB[5]);
                offA[6] = ffma2(xa2, v3.x, offA[6]); offB[6] = ffma2(xb2, v3.x, offB[6]);
                offA[7] = ffma2(xa2, v3.y, offA[7]); offB[7] = ffma2(xb2, v3.y, offB[7]);
                offA[8] = ffma2(xa2, p8,   offA[8]); offB[8] = ffma2(xb2, p8,   offB[8]);
            }
        }
    }

    // ---- Deformable sampling + einsum for one pixel (MASKLESS hot path) ----
    const float fj = (float)j;
    auto deform = [&](const u64* off, float fi, float* res) {
        u64 accP0 = 0ULL, accP1 = 0ULL, accP2 = 0ULL;
        float a20 = CW[660], a21 = CW[661], a22 = CW[662];
        #pragma unroll
        for (int k = 0; k < 9; k++) {
            const int ky = k / 3, kx = k % 3;
            u64 pyx = add2(off[k], pack2(fi + (float)ky, fj + (float)kx));
            float2 q = unpack2(pyx);                      // (py, px)
            int y0 = __float2int_rd(q.x), x0 = __float2int_rd(q.y);
            float wy = q.x - (float)y0, wx = q.y - (float)x0;

            int ry = y0 - ybase, rx = x0 - xbase;
            u64 v01; float v2;
            if (__builtin_expect(((unsigned)ry < (unsigned)(TH - 1)) &
                                 ((unsigned)rx < (unsigned)(TW - 1)), 1)) {
                // Zero-padded tile => unmasked bilinear IS the masked result.
                float a0 = 1.f - wy, b0 = 1.f - wx;
                float w00 = a0 * b0, w01 = a0 * wx, w10 = wy * b0, w11 = wy * wx;
                u64 t01 = mul2(tileP[ry][rx], rep2(w00));
                t01 = ffma2(tileP[ry][rx + 1],     rep2(w01), t01);
                t01 = ffma2(tileP[ry + 1][rx],     rep2(w10), t01);
                t01 = ffma2(tileP[ry + 1][rx + 1], rep2(w11), t01);
                v01 = t01;
                v2 = fmaf(tile2[ry + 1][rx + 1], w11,
                     fmaf(tile2[ry + 1][rx],     w10,
                     fmaf(tile2[ry][rx + 1],     w01, tile2[ry][rx] * w00)));
            } else {
                // Rare: outside staged window -> masked clamped global path.
                float vy0 = ((unsigned)y0       < (unsigned)HH) ? 1.f : 0.f;
                float vy1 = ((unsigned)(y0 + 1) < (unsigned)HH) ? 1.f : 0.f;
                float vx0 = ((unsigned)x0       < (unsigned)WW) ? 1.f : 0.f;
                float vx1 = ((unsigned)(x0 + 1) < (unsigned)WW) ? 1.f : 0.f;
                float a0 = (1.f - wy) * vy0, a1 = wy * vy1;
                float b0 = (1.f - wx) * vx0, b1 = wx * vx1;
                float w00 = a0 * b0, w01 = a0 * b1, w10 = a1 * b0, w11 = a1 * b1;
                int yc0 = min(max(y0, 0), HH - 1), yc1 = min(max(y0 + 1, 0), HH - 1);
                int xc0 = min(max(x0, 0), WW - 1), xc1 = min(max(x0 + 1, 0), WW - 1);
                int i00 = yc0 * WW + xc0, i01 = yc0 * WW + xc1;
                int i10 = yc1 * WW + xc0, i11 = yc1 * WW + xc1;
                u64 t01 = mul2(pack2(__ldg(p0 + i00), __ldg(p1 + i00)), rep2(w00));
                t01 = ffma2(pack2(__ldg(p0 + i01), __ldg(p1 + i01)), rep2(w01), t01);
                t01 = ffma2(pack2(__ldg(p0 + i10), __ldg(p1 + i10)), rep2(w10), t01);
                t01 = ffma2(pack2(__ldg(p0 + i11), __ldg(p1 + i11)), rep2(w11), t01);
                v01 = t01;
                v2 = fmaf(__ldg(p2 + i11), w11,
                     fmaf(__ldg(p2 + i10), w10,
                     fmaf(__ldg(p2 + i01), w01, __ldg(p2 + i00) * w00)));
            }

            ulonglong2 wp01 = ldc128(560 + k * 8);        // (o=0 pair, o=1 pair)
            u64 wp2 = ldc64(560 + k * 8 + 4);             // o=2 pair
            accP0 = ffma2(v01, wp01.x, accP0);
            accP1 = ffma2(v01, wp01.y, accP1);
            accP2 = ffma2(v01, wp2,   accP2);
            a20 = fmaf(v2, CW[632 + k * 3 + 0], a20);
            a21 = fmaf(v2, CW[632 + k * 3 + 1], a21);
            a22 = fmaf(v2, CW[632 + k * 3 + 2], a22);
        }
        float2 r0 = unpack2(accP0), r1 = unpack2(accP1), r2 = unpack2(accP2);
        res[0] = r0.x + r0.y + a20;
        res[1] = r1.x + r1.y + a21;
        res[2] = r2.x + r2.y + a22;
    };

    float rA[3], rB[3];
    deform(offA, (float)iA,        rA);
    deform(offB, (float)iA + 1.f,  rB);

    const size_t plane = (size_t)HO * WO;
    size_t pa = (size_t)b * 3 * plane + (size_t)iA * WO + j;
    out[pa]             = rA[0];
    out[pa + plane]     = rA[1];
    out[pa + 2 * plane] = rA[2];
    pa += WO;
    out[pa]             = rB[0];
    out[pa + plane]     = rB[1];
    out[pa + 2 * plane] = rB[2];
}

extern "C" void kernel_launch(void* const* d_in, const int* in_sizes, int n_in,
                              void* d_out, int out_size)
{
    const float* x      = (const float*)d_in[0];
    const float* conv_w = (const float*)d_in[1];
    const float* conv_b = (const float*)d_in[2];
    const float* dcn_w  = (const float*)d_in[3];
    const float* dcn_b  = (const float*)d_in[4];
    float* out = (float*)d_out;

    float* sp = nullptr;  void* cp = nullptr;
    cudaGetSymbolAddress((void**)&sp, d_scratch);
    cudaGetSymbolAddress(&cp, CW);

    repack<<<1, 544>>>(conv_w, conv_b, dcn_w, dcn_b, sp);
    cudaMemcpyAsync(cp, sp, 672 * sizeof(float), cudaMemcpyDeviceToDevice);

    dim3 blk(32, 4);
    dim3 grd((WO + 31) / 32, (HO + 7) / 8, 16);
    dcn_fused<<<grd, blk>>>(x, out);
}

// round 11
// speedup vs baseline: 1.4534x; 1.0412x over previous
#include <cuda_runtime.h>

#define HH 384
#define WW 384
#define HO 382
#define WO 382
#define RPAD 4
#define TH 18    /* 8 + 2 + 2*RPAD */
#define TW 42    /* 32 + 2 + 2*RPAD */

typedef unsigned long long u64;

// Constant layout (floats):
// [0,540)    cwp[27][20]: conv weight pairs, cwp[jj*20+2p] = (w[2p][jj], w[2p+1][jj])
// [540,558)  conv-bias pairs at 540+2p
// [560,632)  dcn (c0,c1) pairs: (dcn_w[o][0][k], dcn_w[o][1][k]) at 560+k*8+2o (k-major, padded)
// [632,659)  dcn c2: dcn_w[o][2][k] at 632+k*3+o
// [660,663)  dcn bias
__constant__ __align__(16) float CW[672];
__device__ __align__(16) float d_scratch[672];

__device__ __forceinline__ u64 ffma2(u64 a, u64 b, u64 c){
    u64 d; asm("fma.rn.f32x2 %0,%1,%2,%3;" : "=l"(d) : "l"(a), "l"(b), "l"(c)); return d;
}
__device__ __forceinline__ u64 mul2(u64 a, u64 b){
    u64 d; asm("mul.rn.f32x2 %0,%1,%2;" : "=l"(d) : "l"(a), "l"(b)); return d;
}
__device__ __forceinline__ u64 add2(u64 a, u64 b){
    u64 d; asm("add.rn.f32x2 %0,%1,%2;" : "=l"(d) : "l"(a), "l"(b)); return d;
}
__device__ __forceinline__ u64 sub2(u64 a, u64 b){
    u64 d; asm("sub.rn.f32x2 %0,%1,%2;" : "=l"(d) : "l"(a), "l"(b)); return d;
}
__device__ __forceinline__ u64 rep2(float x){
    u64 r; asm("mov.b64 %0,{%1,%1};" : "=l"(r) : "f"(x)); return r;
}
__device__ __forceinline__ u64 pack2(float a, float b){
    u64 r; asm("mov.b64 %0,{%1,%2};" : "=l"(r) : "f"(a), "f"(b)); return r;
}
__device__ __forceinline__ float2 unpack2(u64 v){
    float2 f; asm("mov.b64 {%0,%1},%2;" : "=f"(f.x), "=f"(f.y) : "l"(v)); return f;
}
__device__ __forceinline__ u64 ldc64(int foff){
    return *reinterpret_cast<const u64*>(&CW[foff]);
}
__device__ __forceinline__ ulonglong2 ldc128(int foff){
    return *reinterpret_cast<const ulonglong2*>(&CW[foff]);
}

__global__ void repack(const float* __restrict__ cw, const float* __restrict__ cb,
                       const float* __restrict__ dw, const float* __restrict__ db,
                       float* __restrict__ s)
{
    int t = threadIdx.x;
    if (t < 486) { int o = t / 27, jj = t % 27; s[jj * 20 + o] = cw[t]; }
    else if (t < 504) { s[540 + (t - 486)] = cb[t - 486]; }
    else if (t < 531) {
        int i = t - 504; int o = i / 9, k = i % 9;
        s[560 + k * 8 + 2 * o + 0] = dw[o * 27 + 0 + k];
        s[560 + k * 8 + 2 * o + 1] = dw[o * 27 + 9 + k];
        s[632 + k * 3 + o]         = dw[o * 27 + 18 + k];
    }
    else if (t < 534) { s[660 + (t - 531)] = db[t - 531]; }
    else if (t < 543) { int k = t - 534; s[560 + k * 8 + 6] = 0.f; s[560 + k * 8 + 7] = 0.f; }
}

// Fused offset-conv + deformable conv. Block = 32x4 threads, 2 vertically
// adjacent pixels per thread -> 32x8 output tile. Zero-padded tile (0 outside
// the image) makes the unmasked bilinear equal the reference's masked sum;
// bilinear is computed in lerp form (2 rep2 + 3 sub2 + 3 ffma2 per tap pair).
__global__ __launch_bounds__(128, 6) void dcn_fused(
    const float* __restrict__ x, float* __restrict__ out)
{
    __shared__ u64   tileP[TH][TW];   // 6048 B  (c0,c1) pairs
    __shared__ float tile2[TH][TW];   // 3024 B  c2

    const int tx = threadIdx.x, ty = threadIdx.y;
    const int tid = ty * 32 + tx;
    const int i0 = blockIdx.y * 8, j0 = blockIdx.x * 32, b = blockIdx.z;
    const int ybase = i0 - RPAD, xbase = j0 - RPAD;

    const float* p0 = x + (size_t)b * 3 * HH * WW;
    const float* p1 = p0 + HH * WW;
    const float* p2 = p1 + HH * WW;

    // ---- Stage tile, ZERO outside the image (zero-extension semantics) ----
    #pragma unroll
    for (int it = 0; it < 6; it++) {
        int idx = tid + it * 128;
        if (idx < TH * TW) {
            int r = idx / TW, q = idx % TW;
            int gy = ybase + r, gx = xbase + q;
            bool vin = ((unsigned)gy < (unsigned)HH) & ((unsigned)gx < (unsigned)WW);
            int g = min(max(gy, 0), HH - 1) * WW + min(max(gx, 0), WW - 1);
            float m = vin ? 1.f : 0.f;
            tileP[r][q] = pack2(__ldg(p0 + g) * m, __ldg(p1 + g) * m);
            tile2[r][q] = __ldg(p2 + g) * m;
        }
    }
    __syncthreads();

    const int j  = j0 + tx;
    const int iA = i0 + 2 * ty;            // even; iB = iA+1. Both valid or both not.
    if (j >= WO || iA >= HO) return;

    // ---- Offset conv for both pixels; each weight vector loaded ONCE ----
    u64 offA[9], offB[9];
    #pragma unroll
    for (int p = 0; p < 9; p++) { u64 bp = ldc64(540 + 2 * p); offA[p] = bp; offB[p] = bp; }

    const int lyA = 2 * ty + RPAD, lx = tx + RPAD;

    #pragma unroll
    for (int kx = 0; kx < 3; kx++) {
        u64 rp[4]; float r2[4];
        #pragma unroll
        for (int r = 0; r < 4; r++) { rp[r] = tileP[lyA + r][lx + kx]; r2[r] = tile2[lyA + r][lx + kx]; }
        #pragma unroll
        for (int ky = 0; ky < 3; ky++) {
            float2 fA = unpack2(rp[ky]);
            float2 fB = unpack2(rp[ky + 1]);
            #pragma unroll
            for (int c = 0; c < 3; c++) {
                const int jj = c * 9 + ky * 3 + kx;
                float xa = (c == 0) ? fA.x : (c == 1) ? fA.y : r2[ky];
                float xb = (c == 0) ? fB.x : (c == 1) ? fB.y : r2[ky + 1];
                u64 xa2 = rep2(xa), xb2 = rep2(xb);
                ulonglong2 v0 = ldc128(jj * 20 + 0);
                ulonglong2 v1 = ldc128(jj * 20 + 4);
                ulonglong2 v2 = ldc128(jj * 20 + 8);
                ulonglong2 v3 = ldc128(jj * 20 + 12);
                u64 p8 = ldc64(jj * 20 + 16);
                offA[0] = ffma2(xa2, v0.x, offA[0]); offB[0] = ffma2(xb2, v0.x, offB[0]);
                offA[1] = ffma2(xa2, v0.y, offA[1]); offB[1] = ffma2(xb2, v0.y, offB[1]);
                offA[2] = ffma2(xa2, v1.x, offA[2]); offB[2] = ffma2(xb2, v1.x, offB[2]);
                offA[3] = ffma2(xa2, v1.y, offA[3]); offB[3] = ffma2(xb2, v1.y, offB[3]);
                offA[4] = ffma2(xa2, v2.x, offA[4]); offB[4] = ffma2(xb2, v2.x, offB[4]);
                offA[5] = ffma2(xa2, v2.y, offA[5]); offB[5] = ffma2(xb2, v2.y, offB[5]);
                offA[6] = ffma2(xa2, v3.x, offA[6]); offB[6] = ffma2(xb2, v3.x, offB[6]);
                offA[7] = ffma2(xa2, v3.y, offA[7]); offB[7] = ffma2(xb2, v3.y, offB[7]);
                offA[8] = ffma2(xa2, p8,   offA[8]); offB[8] = ffma2(xb2, p8,   offB[8]);
            }
        }
    }

    // ---- Deformable sampling + einsum for one pixel (lerp-form bilinear) ----
    const float fj = (float)j;
    auto deform = [&](const u64* off, float fi, float* res) {
        u64 accP0 = 0ULL, accP1 = 0ULL, accP2 = 0ULL;
        float a20 = CW[660], a21 = CW[661], a22 = CW[662];
        #pragma unroll
        for (int k = 0; k < 9; k++) {
            const int ky = k / 3, kx = k % 3;
            u64 pyx = add2(off[k], pack2(fi + (float)ky, fj + (float)kx));
            float2 q = unpack2(pyx);                      // (py, px)
            int y0 = __float2int_rd(q.x), x0 = __float2int_rd(q.y);
            float wy = q.x - (float)y0, wx = q.y - (float)x0;

            int ry = y0 - ybase, rx = x0 - xbase;
            u64 v01; float v2;
            if (__builtin_expect(((unsigned)ry < (unsigned)(TH - 1)) &
                                 ((unsigned)rx < (unsigned)(TW - 1)), 1)) {
                // Zero-padded tile: unmasked lerp == masked corner sum.
                u64 wx2 = rep2(wx), wy2 = rep2(wy);
                u64 g00 = tileP[ry][rx],     g01 = tileP[ry][rx + 1];
                u64 g10 = tileP[ry + 1][rx], g11 = tileP[ry + 1][rx + 1];
                u64 r0 = ffma2(wx2, sub2(g01, g00), g00);
                u64 r1 = ffma2(wx2, sub2(g11, g10), g10);
                v01 = ffma2(wy2, sub2(r1, r0), r0);
                float s00 = tile2[ry][rx],     s01 = tile2[ry][rx + 1];
                float s10 = tile2[ry + 1][rx], s11 = tile2[ry + 1][rx + 1];
                float t0 = fmaf(wx, s01 - s00, s00);
                float t1 = fmaf(wx, s11 - s10, s10);
                v2 = fmaf(wy, t1 - t0, t0);
            } else {
                // Rare: outside staged window -> masked clamped global path.
                float vy0 = ((unsigned)y0       < (unsigned)HH) ? 1.f : 0.f;
                float vy1 = ((unsigned)(y0 + 1) < (unsigned)HH) ? 1.f : 0.f;
                float vx0 = ((unsigned)x0       < (unsigned)WW) ? 1.f : 0.f;
                float vx1 = ((unsigned)(x0 + 1) < (unsigned)WW) ? 1.f : 0.f;
                float a0 = (1.f - wy) * vy0, a1 = wy * vy1;
                float b0 = (1.f - wx) * vx0, b1 = wx * vx1;
                float w00 = a0 * b0, w01 = a0 * b1, w10 = a1 * b0, w11 = a1 * b1;
                int yc0 = min(max(y0, 0), HH - 1), yc1 = min(max(y0 + 1, 0), HH - 1);
                int xc0 = min(max(x0, 0), WW - 1), xc1 = min(max(x0 + 1, 0), WW - 1);
                int i00 = yc0 * WW + xc0, i01 = yc0 * WW + xc1;
                int i10 = yc1 * WW + xc0, i11 = yc1 * WW + xc1;
                u64 t01 = mul2(pack2(__ldg(p0 + i00), __ldg(p1 + i00)), rep2(w00));
                t01 = ffma2(pack2(__ldg(p0 + i01), __ldg(p1 + i01)), rep2(w01), t01);
                t01 = ffma2(pack2(__ldg(p0 + i10), __ldg(p1 + i10)), rep2(w10), t01);
                t01 = ffma2(pack2(__ldg(p0 + i11), __ldg(p1 + i11)), rep2(w11), t01);
                v01 = t01;
                v2 = fmaf(__ldg(p2 + i11), w11,
                     fmaf(__ldg(p2 + i10), w10,
                     fmaf(__ldg(p2 + i01), w01, __ldg(p2 + i00) * w00)));
            }

            ulonglong2 wp01 = ldc128(560 + k * 8);        // (o=0 pair, o=1 pair)
            u64 wp2 = ldc64(560 + k * 8 + 4);             // o=2 pair
            accP0 = ffma2(v01, wp01.x, accP0);
            accP1 = ffma2(v01, wp01.y, accP1);
            accP2 = ffma2(v01, wp2,   accP2);
            a20 = fmaf(v2, CW[632 + k * 3 + 0], a20);
            a21 = fmaf(v2, CW[632 + k * 3 + 1], a21);
            a22 = fmaf(v2, CW[632 + k * 3 + 2], a22);
        }
        float2 r0 = unpack2(accP0), r1 = unpack2(accP1), r2 = unpack2(accP2);
        res[0] = r0.x + r0.y + a20;
        res[1] = r1.x + r1.y + a21;
        res[2] = r2.x + r2.y + a22;
    };

    float rA[3], rB[3];
    deform(offA, (float)iA,        rA);
    deform(offB, (float)iA + 1.f,  rB);

    const size_t plane = (size_t)HO * WO;
    size_t pa = (size_t)b * 3 * plane + (size_t)iA * WO + j;
    out[pa]             = rA[0];
    out[pa + plane]     = rA[1];
    out[pa + 2 * plane] = rA[2];
    pa += WO;
    out[pa]             = rB[0];
    out[pa + plane]     = rB[1];
    out[pa + 2 * plane] = rB[2];
}

extern "C" void kernel_launch(void* const* d_in, const int* in_sizes, int n_in,
                              void* d_out, int out_size)
{
    const float* x      = (const float*)d_in[0];
    const float* conv_w = (const float*)d_in[1];
    const float* conv_b = (const float*)d_in[2];
    const float* dcn_w  = (const float*)d_in[3];
    const float* dcn_b  = (const float*)d_in[4];
    float* out = (float*)d_out;

    float* sp = nullptr;  void* cp = nullptr;
    cudaGetSymbolAddress((void**)&sp, d_scratch);
    cudaGetSymbolAddress(&cp, CW);

    repack<<<1, 544>>>(conv_w, conv_b, dcn_w, dcn_b, sp);
    cudaMemcpyAsync(cp, sp, 672 * sizeof(float), cudaMemcpyDeviceToDevice);

    dim3 blk(32, 4);
    dim3 grd((WO + 31) / 32, (HO + 7) / 8, 16);
    dcn_fused<<<grd, blk>>>(x, out);
}